// round 13
// baseline (speedup 1.0000x reference)
#include <cuda_runtime.h>
#include <cstdint>

#define M_DIM 8192
#define N_DIM 4096
#define K_DIM 4096

#define MT 128
#define NT 128
#define KT 32
#define STAGES 3
#define KITERS (K_DIM / KT)          // 128
#define THREADS 128
#define NTILES  ((M_DIM / MT) * (N_DIM / NT))   // 2048

#define A_STAGE_BYTES (MT * KT * 4)  // 16384
#define B_STAGE_BYTES (NT * KT * 4)  // 16384
#define STAGE_BYTES   (A_STAGE_BYTES + B_STAGE_BYTES)   // 32768
#define SMEM_BYTES    (STAGES * STAGE_BYTES)            // 98304

// Scratch: symmetrized + tf32-rounded weight
__device__ float g_wsym[(size_t)N_DIM * K_DIM];

// ---------------- helpers ----------------
__device__ __forceinline__ uint32_t smem_u32(const void* p) {
    uint32_t a;
    asm("{ .reg .u64 t; cvta.to.shared.u64 t, %1; cvt.u32.u64 %0, t; }" : "=r"(a) : "l"(p));
    return a;
}
__device__ __forceinline__ uint32_t f2tf32(float f) {
    uint32_t r;
    asm("cvt.rna.tf32.f32 %0, %1;" : "=r"(r) : "f"(f));
    return r;
}
__device__ __forceinline__ void cp_async16(uint32_t dst, const void* src) {
    asm volatile("cp.async.cg.shared.global [%0], [%1], 16;" :: "r"(dst), "l"(src) : "memory");
}
#define CP_COMMIT() asm volatile("cp.async.commit_group;" ::: "memory")
#define CP_WAIT1()  asm volatile("cp.async.wait_group 1;" ::: "memory")

// ldmatrix x4: four 8x(16B) matrices -> 4 regs/thread
__device__ __forceinline__ void ldsm4(uint32_t& d0, uint32_t& d1, uint32_t& d2,
                                      uint32_t& d3, uint32_t a) {
    asm volatile("ldmatrix.sync.aligned.m8n8.x4.shared.b16 {%0,%1,%2,%3}, [%4];"
                 : "=r"(d0), "=r"(d1), "=r"(d2), "=r"(d3) : "r"(a));
}

__device__ __forceinline__ void mma_tf32(float* c, const uint32_t* a, const uint32_t* b) {
    asm volatile(
        "mma.sync.aligned.m16n8k8.row.col.f32.tf32.tf32.f32 "
        "{%0,%1,%2,%3}, {%4,%5,%6,%7}, {%8,%9}, {%0,%1,%2,%3};"
        : "+f"(c[0]), "+f"(c[1]), "+f"(c[2]), "+f"(c[3])
        : "r"(a[0]), "r"(a[1]), "r"(a[2]), "r"(a[3]), "r"(b[0]), "r"(b[1]));
}

// tile index -> (m0, n0): bands of 8 M-tiles over all N; all shifts (256 tiles/band)
__device__ __forceinline__ void tile_coords(int t, int& m0, int& n0) {
    int band = t >> 8;
    int inb = t & 255;
    m0 = ((band << 3) + (inb & 7)) * MT;
    n0 = (inb >> 3) * NT;
}

// ---------------- pre-pass: symmetrize + tf32-round weight (float4, R8-proven) ----------------
__global__ void symmetrize_kernel(const float* __restrict__ w) {
    int idx = blockIdx.x * blockDim.x + threadIdx.x;   // 0 .. 4,194,303
    int r = idx >> 10;                                 // 1024 float4 per row
    int c4 = (idx & 1023) * 4;
    float4 a = *(const float4*)(w + (size_t)r * K_DIM + c4);
    float o[4] = {a.x, a.y, a.z, a.w};
    if (r < 4092 && c4 < 4092) {     // 4092 % 4 == 0: group never straddles edge
        int br = r / 12, ir = r - br * 12;
        #pragma unroll
        for (int j = 0; j < 4; j++) {
            int c = c4 + j;
            int bc = c / 12, ic = c - bc * 12;
            float b = w[(size_t)(br * 12 + ic) * K_DIM + bc * 12 + ir];
            o[j] = 0.5f * (o[j] + b);
        }
    }
    uint4 v;
    v.x = f2tf32(o[0]); v.y = f2tf32(o[1]); v.z = f2tf32(o[2]); v.w = f2tf32(o[3]);
    *(uint4*)((uint32_t*)g_wsym + (size_t)r * K_DIM + c4) = v;
}

// ---------------- main GEMM: static persistent CTAs + cross-tile prefetch ----------------
__global__ void __launch_bounds__(THREADS, 2)
gemm_tf32_kernel(const float* __restrict__ x, const float* __restrict__ bias,
                 float* __restrict__ out) {
    extern __shared__ char smem[];
    const uint32_t sb = smem_u32(smem);

    const int tid = threadIdx.x;
    const int wid = tid >> 5;
    const int lane = tid & 31;
    const int g = lane >> 2;
    const int tig = lane & 3;

    // warp tile: 64x64; warp grid 2 (m) x 2 (n)
    const int wm = (wid & 1) * 64;
    const int wn = (wid >> 1) * 64;

    // ldmatrix per-lane geometry (same fragment layout as scalar path)
    const int lane7 = lane & 7;
    const int laneA_row = ((lane >> 3) & 1) * 8 + lane7;
    const int khalfA = lane >> 4;
    const int laneB_row = (lane >> 4) * 8 + lane7;
    const int khalfB = (lane >> 3) & 1;

    uint32_t cA[4], cB[4];
    #pragma unroll
    for (int ks = 0; ks < 4; ks++) {
        cA[ks] = (uint32_t)(((2 * ks + khalfA) ^ lane7) << 4);
        cB[ks] = (uint32_t)(((2 * ks + khalfB) ^ lane7) << 4);
    }

    // producer: A 1024 16B chunks (8/thread), B 1024 (8/thread); NO commit here
    auto issue_stage = [&](int s, int m0_, int n0_, int kt) {
        const uint32_t aBase = sb + (uint32_t)s * STAGE_BYTES;
        const uint32_t bBase = aBase + A_STAGE_BYTES;
        const int k0 = kt * KT;
        #pragma unroll
        for (int i = 0; i < 8; i++) {
            int id = tid + i * THREADS;
            int row = id >> 3, ch = id & 7;
            const float* src = x + (size_t)(m0_ + row) * K_DIM + k0 + ch * 4;
            cp_async16(aBase + (uint32_t)row * 128u + (uint32_t)((ch ^ (row & 7)) << 4), src);
        }
        #pragma unroll
        for (int i = 0; i < 8; i++) {
            int id = tid + i * THREADS;
            int row = id >> 3, ch = id & 7;
            const float* src = g_wsym + (size_t)(n0_ + row) * K_DIM + k0 + ch * 4;
            cp_async16(bBase + (uint32_t)row * 128u + (uint32_t)((ch ^ (row & 7)) << 4), src);
        }
    };

    int t = blockIdx.x;
    int m0, n0;
    tile_coords(t, m0, n0);

    float acc[4][8][4];
    #pragma unroll
    for (int mt = 0; mt < 4; mt++)
        #pragma unroll
        for (int nt = 0; nt < 8; nt++)
            #pragma unroll
            for (int i = 0; i < 4; i++) acc[mt][nt][i] = 0.0f;

    // prologue: fill 2 of 3 stages for the first tile
    issue_stage(0, m0, n0, 0); CP_COMMIT();
    issue_stage(1, m0, n0, 1); CP_COMMIT();

    int s = 0;
    for (;;) {
        for (int kt = 0; kt < KITERS; kt++) {
            CP_WAIT1();
            __syncthreads();

            const uint32_t aStage = sb + (uint32_t)s * STAGE_BYTES;
            const uint32_t bStage = aStage + A_STAGE_BYTES;
            const uint32_t aB = aStage + (uint32_t)(wm + laneA_row) * 128u;
            const uint32_t bB = bStage + (uint32_t)(wn + laneB_row) * 128u;

            #pragma unroll
            for (int ks = 0; ks < 4; ks++) {
                uint32_t af[4][4];
                uint32_t bf[8][2];
                #pragma unroll
                for (int mt = 0; mt < 4; mt++)
                    ldsm4(af[mt][0], af[mt][1], af[mt][2], af[mt][3],
                          aB + (uint32_t)mt * 2048u + cA[ks]);
                #pragma unroll
                for (int p = 0; p < 4; p++)
                    ldsm4(bf[2 * p][0], bf[2 * p][1], bf[2 * p + 1][0], bf[2 * p + 1][1],
                          bB + (uint32_t)p * 2048u + cB[ks]);
                #pragma unroll
                for (int mt = 0; mt < 4; mt++)
                    #pragma unroll
                    for (int nt = 0; nt < 8; nt++)
                        mma_tf32(acc[mt][nt], af[mt], bf[nt]);

                if (ks == 0) {   // overlap cp.async issue with MMA work
                    int ws = s + 2; if (ws >= STAGES) ws -= STAGES;
                    if (kt + 2 < KITERS) {
                        issue_stage(ws, m0, n0, kt + 2);          // this tile
                    } else {
                        int tn = t + (int)gridDim.x;              // next tile (computed here only)
                        if (tn < NTILES) {
                            int nm0, nn0;
                            tile_coords(tn, nm0, nn0);
                            issue_stage(ws, nm0, nn0, kt + 2 - KITERS);
                        }
                    }
                    CP_COMMIT();   // exactly one commit per kt (possibly empty)
                }
            }

            if (++s == STAGES) s = 0;
        }

        // ---- per-tile epilogue: bias + store (overlaps next tile's cp.asyncs) ----
        #pragma unroll
        for (int mt = 0; mt < 4; mt++) {
            int m = m0 + wm + mt * 16 + g;
            float* r0 = out + (size_t)m * N_DIM + n0 + wn;
            float* r1 = r0 + (size_t)8 * N_DIM;
            #pragma unroll
            for (int nt = 0; nt < 8; nt++) {
                int n = n0 + wn + nt * 8 + 2 * tig;
                float b0 = __ldg(bias + n);
                float b1 = __ldg(bias + n + 1);
                float2 v0, v1;
                v0.x = acc[mt][nt][0] + b0;
                v0.y = acc[mt][nt][1] + b1;
                v1.x = acc[mt][nt][2] + b0;
                v1.y = acc[mt][nt][3] + b1;
                *(float2*)(r0 + nt * 8 + 2 * tig) = v0;
                *(float2*)(r1 + nt * 8 + 2 * tig) = v1;
            }
        }

        t += (int)gridDim.x;
        if (t >= NTILES) break;
        tile_coords(t, m0, n0);

        #pragma unroll
        for (int mt = 0; mt < 4; mt++)
            #pragma unroll
            for (int nt = 0; nt < 8; nt++)
                #pragma unroll
                for (int i = 0; i < 4; i++) acc[mt][nt][i] = 0.0f;
    }
}

// ---------------- launch ----------------
extern "C" void kernel_launch(void* const* d_in, const int* in_sizes, int n_in,
                              void* d_out, int out_size) {
    const float* x = (const float*)d_in[0];       // [8192, 4096]
    const float* w = (const float*)d_in[1];       // [4096, 4096]
    const float* bias = (const float*)d_in[2];    // [4096]
    float* out = (float*)d_out;                   // [8192, 4096]

    symmetrize_kernel<<<(N_DIM * (size_t)K_DIM) / 4 / 256, 256>>>(w);

    static int n_sm = 0;
    if (n_sm == 0) {
        if (cudaDeviceGetAttribute(&n_sm, cudaDevAttrMultiProcessorCount, 0) != cudaSuccess
            || n_sm <= 0)
            n_sm = 148;
    }
    int grid = 2 * n_sm;
    if (grid > NTILES) grid = NTILES;

    cudaFuncSetAttribute(gemm_tf32_kernel,
                         cudaFuncAttributeMaxDynamicSharedMemorySize, SMEM_BYTES);
    gemm_tf32_kernel<<<grid, THREADS, SMEM_BYTES>>>(x, bias, out);
}

// round 14
// speedup vs baseline: 1.8941x; 1.8941x over previous
#include <cuda_runtime.h>
#include <cuda_fp16.h>
#include <cstdint>

#define M_DIM 8192
#define N_DIM 4096
#define K_DIM 4096

#define MT 128
#define NT 128
#define KT 64                        // fp16 elements per stage row (= 128B)
#define STAGES 3
#define KITERS (K_DIM / KT)          // 64
#define THREADS 128

#define A_STAGE_BYTES (MT * KT * 2)  // 16384
#define B_STAGE_BYTES (NT * KT * 2)  // 16384
#define STAGE_BYTES   (A_STAGE_BYTES + B_STAGE_BYTES)   // 32768
#define SMEM_BYTES    (STAGES * STAGE_BYTES)            // 98304

// Scratch: fp16 copies (x converted; weight symmetrized + converted)
__device__ __half g_xh[(size_t)M_DIM * K_DIM];     // 64 MB
__device__ __half g_wsym[(size_t)N_DIM * K_DIM];   // 32 MB

// ---------------- helpers ----------------
__device__ __forceinline__ uint32_t smem_u32(const void* p) {
    uint32_t a;
    asm("{ .reg .u64 t; cvta.to.shared.u64 t, %1; cvt.u32.u64 %0, t; }" : "=r"(a) : "l"(p));
    return a;
}
__device__ __forceinline__ void cp_async16(uint32_t dst, const void* src) {
    asm volatile("cp.async.cg.shared.global [%0], [%1], 16;" :: "r"(dst), "l"(src) : "memory");
}
#define CP_COMMIT() asm volatile("cp.async.commit_group;" ::: "memory")
#define CP_WAIT1()  asm volatile("cp.async.wait_group 1;" ::: "memory")

// ldmatrix x4: four 8x8 b16 matrices -> 4 regs/thread
__device__ __forceinline__ void ldsm4(uint32_t& d0, uint32_t& d1, uint32_t& d2,
                                      uint32_t& d3, uint32_t a) {
    asm volatile("ldmatrix.sync.aligned.m8n8.x4.shared.b16 {%0,%1,%2,%3}, [%4];"
                 : "=r"(d0), "=r"(d1), "=r"(d2), "=r"(d3) : "r"(a));
}

// fp16 MMA, fp32 accumulate: same fragment register counts as tf32 m16n8k8, K=16
__device__ __forceinline__ void mma_f16(float* c, const uint32_t* a, const uint32_t* b) {
    asm volatile(
        "mma.sync.aligned.m16n8k16.row.col.f32.f16.f16.f32 "
        "{%0,%1,%2,%3}, {%4,%5,%6,%7}, {%8,%9}, {%0,%1,%2,%3};"
        : "+f"(c[0]), "+f"(c[1]), "+f"(c[2]), "+f"(c[3])
        : "r"(a[0]), "r"(a[1]), "r"(a[2]), "r"(a[3]), "r"(b[0]), "r"(b[1]));
}

// ---------------- pre-pass: convert x to fp16 (8 floats/thread) ----------------
__global__ void convert_x_kernel(const float* __restrict__ x) {
    size_t i = (size_t)blockIdx.x * blockDim.x + threadIdx.x;  // 4.19M threads
    const float4* s = (const float4*)(x + i * 8);
    float4 a = s[0], b = s[1];
    __half2 h0 = __floats2half2_rn(a.x, a.y);
    __half2 h1 = __floats2half2_rn(a.z, a.w);
    __half2 h2 = __floats2half2_rn(b.x, b.y);
    __half2 h3 = __floats2half2_rn(b.z, b.w);
    uint4 v;
    v.x = *(uint32_t*)&h0; v.y = *(uint32_t*)&h1;
    v.z = *(uint32_t*)&h2; v.w = *(uint32_t*)&h3;
    *(uint4*)((__half*)g_xh + i * 8) = v;
}

// ---------------- pre-pass: symmetrize + fp16-convert weight ----------------
__global__ void symmetrize_kernel(const float* __restrict__ w) {
    int idx = blockIdx.x * blockDim.x + threadIdx.x;   // 0 .. 4,194,303
    int r = idx >> 10;                                 // 1024 groups-of-4 per row
    int c4 = (idx & 1023) * 4;
    float4 a = *(const float4*)(w + (size_t)r * K_DIM + c4);
    float o[4] = {a.x, a.y, a.z, a.w};
    if (r < 4092 && c4 < 4092) {     // 4092 % 4 == 0: group never straddles edge
        int br = r / 12, ir = r - br * 12;
        #pragma unroll
        for (int j = 0; j < 4; j++) {
            int c = c4 + j;
            int bc = c / 12, ic = c - bc * 12;
            float b = w[(size_t)(br * 12 + ic) * K_DIM + bc * 12 + ir];
            o[j] = 0.5f * (o[j] + b);
        }
    }
    __half2 h0 = __floats2half2_rn(o[0], o[1]);
    __half2 h1 = __floats2half2_rn(o[2], o[3]);
    uint2 v;
    v.x = *(uint32_t*)&h0; v.y = *(uint32_t*)&h1;
    *(uint2*)((__half*)g_wsym + (size_t)r * K_DIM + c4) = v;
}

// ---------------- main GEMM (R11 structure, fp16 operands) ----------------
__global__ void __launch_bounds__(THREADS, 2)
gemm_f16_kernel(const float* __restrict__ bias, float* __restrict__ out) {
    extern __shared__ char smem[];
    const uint32_t sb = smem_u32(smem);

    const int tid = threadIdx.x;
    const int wid = tid >> 5;
    const int lane = tid & 31;
    const int g = lane >> 2;        // groupID 0..7
    const int tig = lane & 3;       // thread-in-group 0..3

    // warp tile: 64x64; warp grid 2 (m) x 2 (n)
    const int wm = (wid & 1) * 64;
    const int wn = (wid >> 1) * 64;

    // ldmatrix per-lane geometry (identical to the proven tf32 mapping):
    // A x4: (r0-7,k0-7)(r8-15,k0-7)(r0-7,k8-15)(r8-15,k8-15) -> a0..a3
    // B x4: (n0-7,klo)(n0-7,khi)(n8-15,klo)(n8-15,khi) -> bf[2p],bf[2p+1]
    const int lane7 = lane & 7;
    const int laneA_row = ((lane >> 3) & 1) * 8 + lane7;
    const int khalfA = lane >> 4;
    const int laneB_row = (lane >> 4) * 8 + lane7;
    const int khalfB = (lane >> 3) & 1;

    uint32_t cA[4], cB[4];
    #pragma unroll
    for (int ks = 0; ks < 4; ks++) {   // ks = one k16 step; chunks 2ks (k0-7), 2ks+1 (k8-15)
        cA[ks] = (uint32_t)(((2 * ks + khalfA) ^ lane7) << 4);
        cB[ks] = (uint32_t)(((2 * ks + khalfB) ^ lane7) << 4);
    }

    // CTA raster: bands of 8 M-tiles over all N (keeps W band L2-resident)
    const int num_n = N_DIM / NT;              // 32
    const int tiles_per_band = 8 * num_n;      // 256
    int t = blockIdx.x;
    int band = t / tiles_per_band;
    int inb = t - band * tiles_per_band;
    const int m0 = (band * 8 + (inb & 7)) * MT;
    const int n0 = (inb >> 3) * NT;

    // preload bias
    float bias_r[8][2];
    #pragma unroll
    for (int nt = 0; nt < 8; nt++) {
        int n = n0 + wn + nt * 8 + 2 * tig;
        bias_r[nt][0] = __ldg(bias + n);
        bias_r[nt][1] = __ldg(bias + n + 1);
    }

    float acc[4][8][4];
    #pragma unroll
    for (int mt = 0; mt < 4; mt++)
        #pragma unroll
        for (int nt = 0; nt < 8; nt++)
            #pragma unroll
            for (int i = 0; i < 4; i++) acc[mt][nt][i] = 0.0f;

    // producer: A 1024 16B chunks (8/thread), B 1024 (8/thread); 16B = 8 halves
    auto issue_stage = [&](int s, int kt) {
        const uint32_t aBase = sb + (uint32_t)s * STAGE_BYTES;
        const uint32_t bBase = aBase + A_STAGE_BYTES;
        const int k0 = kt * KT;
        #pragma unroll
        for (int i = 0; i < 8; i++) {
            int id = tid + i * THREADS;          // 0..1023
            int row = id >> 3, ch = id & 7;
            const __half* src = (const __half*)g_xh + (size_t)(m0 + row) * K_DIM + k0 + ch * 8;
            cp_async16(aBase + (uint32_t)row * 128u + (uint32_t)((ch ^ (row & 7)) << 4), src);
        }
        #pragma unroll
        for (int i = 0; i < 8; i++) {
            int id = tid + i * THREADS;
            int row = id >> 3, ch = id & 7;
            const __half* src = (const __half*)g_wsym + (size_t)(n0 + row) * K_DIM + k0 + ch * 8;
            cp_async16(bBase + (uint32_t)row * 128u + (uint32_t)((ch ^ (row & 7)) << 4), src);
        }
        CP_COMMIT();
    };

    // prologue: fill 2 of 3 stages
    issue_stage(0, 0);
    issue_stage(1, 1);

    int s = 0;
    for (int kt = 0; kt < KITERS; kt++) {
        CP_WAIT1();
        __syncthreads();

        const uint32_t aStage = sb + (uint32_t)s * STAGE_BYTES;
        const uint32_t bStage = aStage + A_STAGE_BYTES;
        const uint32_t aB = aStage + (uint32_t)(wm + laneA_row) * 128u;
        const uint32_t bB = bStage + (uint32_t)(wn + laneB_row) * 128u;

        #pragma unroll
        for (int ks = 0; ks < 4; ks++) {   // 4 x k16 = KT
            uint32_t af[4][4];
            uint32_t bf[8][2];
            #pragma unroll
            for (int mt = 0; mt < 4; mt++)
                ldsm4(af[mt][0], af[mt][1], af[mt][2], af[mt][3],
                      aB + (uint32_t)mt * 2048u + cA[ks]);
            #pragma unroll
            for (int p = 0; p < 4; p++)
                ldsm4(bf[2 * p][0], bf[2 * p][1], bf[2 * p + 1][0], bf[2 * p + 1][1],
                      bB + (uint32_t)p * 2048u + cB[ks]);
            #pragma unroll
            for (int mt = 0; mt < 4; mt++)
                #pragma unroll
                for (int nt = 0; nt < 8; nt++)
                    mma_f16(acc[mt][nt], af[mt], bf[nt]);

            if (ks == 0) {   // overlap cp.async issue with MMA work
                if (kt + 2 < KITERS) {
                    int ws = s + 2; if (ws >= STAGES) ws -= STAGES;
                    issue_stage(ws, kt + 2);
                } else {
                    CP_COMMIT();   // keep group count consistent
                }
            }
        }

        if (++s == STAGES) s = 0;
    }

    // ---- epilogue: bias + store (same C fragment layout as tf32 path) ----
    #pragma unroll
    for (int mt = 0; mt < 4; mt++) {
        int m = m0 + wm + mt * 16 + g;
        float* r0 = out + (size_t)m * N_DIM + n0 + wn;
        float* r1 = r0 + (size_t)8 * N_DIM;
        #pragma unroll
        for (int nt = 0; nt < 8; nt++) {
            float2 v0, v1;
            v0.x = acc[mt][nt][0] + bias_r[nt][0];
            v0.y = acc[mt][nt][1] + bias_r[nt][1];
            v1.x = acc[mt][nt][2] + bias_r[nt][0];
            v1.y = acc[mt][nt][3] + bias_r[nt][1];
            *(float2*)(r0 + nt * 8 + 2 * tig) = v0;
            *(float2*)(r1 + nt * 8 + 2 * tig) = v1;
        }
    }
}

// ---------------- launch ----------------
extern "C" void kernel_launch(void* const* d_in, const int* in_sizes, int n_in,
                              void* d_out, int out_size) {
    const float* x = (const float*)d_in[0];       // [8192, 4096]
    const float* w = (const float*)d_in[1];       // [4096, 4096]
    const float* bias = (const float*)d_in[2];    // [4096]
    float* out = (float*)d_out;                   // [8192, 4096]

    convert_x_kernel<<<(M_DIM * (size_t)K_DIM) / 8 / 256, 256>>>(x);
    symmetrize_kernel<<<(N_DIM * (size_t)K_DIM) / 4 / 256, 256>>>(w);

    cudaFuncSetAttribute(gemm_f16_kernel,
                         cudaFuncAttributeMaxDynamicSharedMemorySize, SMEM_BYTES);
    const int grid = (M_DIM / MT) * (N_DIM / NT);  // 2048
    gemm_f16_kernel<<<grid, THREADS, SMEM_BYTES>>>(bias, out);
}

// round 15
// speedup vs baseline: 1.9021x; 1.0042x over previous
#include <cuda_runtime.h>
#include <cuda_fp16.h>
#include <cstdint>

#define M_DIM 8192
#define N_DIM 4096
#define K_DIM 4096

#define MT 128
#define NT 128
#define KT 64                        // fp16 elements per stage row (= 128B)
#define STAGES 3
#define KITERS (K_DIM / KT)          // 64
#define THREADS 128

#define A_STAGE_BYTES (MT * KT * 2)  // 16384
#define B_STAGE_BYTES (NT * KT * 2)  // 16384
#define STAGE_BYTES   (A_STAGE_BYTES + B_STAGE_BYTES)   // 32768
#define SMEM_BYTES    (STAGES * STAGE_BYTES)            // 98304

// blocks in the fused pre-pass
#define XCONV_BLOCKS 16384           // (M*K)/8/256
#define WSYM_BLOCKS  16384           // (N*K)/4/256

// Scratch: fp16 copies (x converted; weight symmetrized + converted)
__device__ __half g_xh[(size_t)M_DIM * K_DIM];     // 64 MB
__device__ __half g_wsym[(size_t)N_DIM * K_DIM];   // 32 MB

// ---------------- helpers ----------------
__device__ __forceinline__ uint32_t smem_u32(const void* p) {
    uint32_t a;
    asm("{ .reg .u64 t; cvta.to.shared.u64 t, %1; cvt.u32.u64 %0, t; }" : "=r"(a) : "l"(p));
    return a;
}
__device__ __forceinline__ void cp_async16(uint32_t dst, const void* src) {
    asm volatile("cp.async.cg.shared.global [%0], [%1], 16;" :: "r"(dst), "l"(src) : "memory");
}
#define CP_COMMIT() asm volatile("cp.async.commit_group;" ::: "memory")
#define CP_WAIT1()  asm volatile("cp.async.wait_group 1;" ::: "memory")

// ldmatrix x4: four 8x8 b16 matrices -> 4 regs/thread
__device__ __forceinline__ void ldsm4(uint32_t& d0, uint32_t& d1, uint32_t& d2,
                                      uint32_t& d3, uint32_t a) {
    asm volatile("ldmatrix.sync.aligned.m8n8.x4.shared.b16 {%0,%1,%2,%3}, [%4];"
                 : "=r"(d0), "=r"(d1), "=r"(d2), "=r"(d3) : "r"(a));
}

// fp16 MMA, fp32 accumulate
__device__ __forceinline__ void mma_f16(float* c, const uint32_t* a, const uint32_t* b) {
    asm volatile(
        "mma.sync.aligned.m16n8k16.row.col.f32.f16.f16.f32 "
        "{%0,%1,%2,%3}, {%4,%5,%6,%7}, {%8,%9}, {%0,%1,%2,%3};"
        : "+f"(c[0]), "+f"(c[1]), "+f"(c[2]), "+f"(c[3])
        : "r"(a[0]), "r"(a[1]), "r"(a[2]), "r"(a[3]), "r"(b[0]), "r"(b[1]));
}

// ---------------- fused pre-pass: convert x + symmetrize/convert w ----------------
__global__ void prep_kernel(const float* __restrict__ x, const float* __restrict__ w) {
    int b = blockIdx.x;
    if (b < XCONV_BLOCKS) {
        // phase 1: x fp32 -> fp16, 8 floats/thread
        size_t i = (size_t)b * blockDim.x + threadIdx.x;
        const float4* s = (const float4*)(x + i * 8);
        float4 a = s[0], c = s[1];
        __half2 h0 = __floats2half2_rn(a.x, a.y);
        __half2 h1 = __floats2half2_rn(a.z, a.w);
        __half2 h2 = __floats2half2_rn(c.x, c.y);
        __half2 h3 = __floats2half2_rn(c.z, c.w);
        uint4 v;
        v.x = *(uint32_t*)&h0; v.y = *(uint32_t*)&h1;
        v.z = *(uint32_t*)&h2; v.w = *(uint32_t*)&h3;
        *(uint4*)((__half*)g_xh + i * 8) = v;
    } else {
        // phase 2: w 12x12-block symmetrize + fp16 convert, 4 floats/thread
        int idx = (b - XCONV_BLOCKS) * blockDim.x + threadIdx.x;  // 0 .. 4,194,303
        int r = idx >> 10;                                        // 1024 groups-of-4/row
        int c4 = (idx & 1023) * 4;
        float4 a = *(const float4*)(w + (size_t)r * K_DIM + c4);
        float o[4] = {a.x, a.y, a.z, a.w};
        if (r < 4092 && c4 < 4092) {   // 4092 % 4 == 0: group never straddles edge
            int br = r / 12, ir = r - br * 12;
            #pragma unroll
            for (int j = 0; j < 4; j++) {
                int c = c4 + j;
                int bc = c / 12, ic = c - bc * 12;
                float t = w[(size_t)(br * 12 + ic) * K_DIM + bc * 12 + ir];
                o[j] = 0.5f * (o[j] + t);
            }
        }
        __half2 h0 = __floats2half2_rn(o[0], o[1]);
        __half2 h1 = __floats2half2_rn(o[2], o[3]);
        uint2 v;
        v.x = *(uint32_t*)&h0; v.y = *(uint32_t*)&h1;
        *(uint2*)((__half*)g_wsym + (size_t)r * K_DIM + c4) = v;
    }
}

// ---------------- main GEMM (R14-frozen: fp16 operands, R11 structure) ----------------
__global__ void __launch_bounds__(THREADS, 2)
gemm_f16_kernel(const float* __restrict__ bias, float* __restrict__ out) {
    extern __shared__ char smem[];
    const uint32_t sb = smem_u32(smem);

    const int tid = threadIdx.x;
    const int wid = tid >> 5;
    const int lane = tid & 31;
    const int g = lane >> 2;        // groupID 0..7
    const int tig = lane & 3;       // thread-in-group 0..3

    // warp tile: 64x64; warp grid 2 (m) x 2 (n)
    const int wm = (wid & 1) * 64;
    const int wn = (wid >> 1) * 64;

    // ldmatrix per-lane geometry
    const int lane7 = lane & 7;
    const int laneA_row = ((lane >> 3) & 1) * 8 + lane7;
    const int khalfA = lane >> 4;
    const int laneB_row = (lane >> 4) * 8 + lane7;
    const int khalfB = (lane >> 3) & 1;

    uint32_t cA[4], cB[4];
    #pragma unroll
    for (int ks = 0; ks < 4; ks++) {   // ks = one k16 step
        cA[ks] = (uint32_t)(((2 * ks + khalfA) ^ lane7) << 4);
        cB[ks] = (uint32_t)(((2 * ks + khalfB) ^ lane7) << 4);
    }

    // CTA raster: bands of 8 M-tiles over all N (keeps W band L2-resident)
    const int num_n = N_DIM / NT;              // 32
    const int tiles_per_band = 8 * num_n;      // 256
    int t = blockIdx.x;
    int band = t / tiles_per_band;
    int inb = t - band * tiles_per_band;
    const int m0 = (band * 8 + (inb & 7)) * MT;
    const int n0 = (inb >> 3) * NT;

    // preload bias
    float bias_r[8][2];
    #pragma unroll
    for (int nt = 0; nt < 8; nt++) {
        int n = n0 + wn + nt * 8 + 2 * tig;
        bias_r[nt][0] = __ldg(bias + n);
        bias_r[nt][1] = __ldg(bias + n + 1);
    }

    float acc[4][8][4];
    #pragma unroll
    for (int mt = 0; mt < 4; mt++)
        #pragma unroll
        for (int nt = 0; nt < 8; nt++)
            #pragma unroll
            for (int i = 0; i < 4; i++) acc[mt][nt][i] = 0.0f;

    // producer: A 1024 16B chunks (8/thread), B 1024 (8/thread)
    auto issue_stage = [&](int s, int kt) {
        const uint32_t aBase = sb + (uint32_t)s * STAGE_BYTES;
        const uint32_t bBase = aBase + A_STAGE_BYTES;
        const int k0 = kt * KT;
        #pragma unroll
        for (int i = 0; i < 8; i++) {
            int id = tid + i * THREADS;          // 0..1023
            int row = id >> 3, ch = id & 7;
            const __half* src = (const __half*)g_xh + (size_t)(m0 + row) * K_DIM + k0 + ch * 8;
            cp_async16(aBase + (uint32_t)row * 128u + (uint32_t)((ch ^ (row & 7)) << 4), src);
        }
        #pragma unroll
        for (int i = 0; i < 8; i++) {
            int id = tid + i * THREADS;
            int row = id >> 3, ch = id & 7;
            const __half* src = (const __half*)g_wsym + (size_t)(n0 + row) * K_DIM + k0 + ch * 8;
            cp_async16(bBase + (uint32_t)row * 128u + (uint32_t)((ch ^ (row & 7)) << 4), src);
        }
        CP_COMMIT();
    };

    // prologue: fill 2 of 3 stages
    issue_stage(0, 0);
    issue_stage(1, 1);

    int s = 0;
    for (int kt = 0; kt < KITERS; kt++) {
        CP_WAIT1();
        __syncthreads();

        const uint32_t aStage = sb + (uint32_t)s * STAGE_BYTES;
        const uint32_t bStage = aStage + A_STAGE_BYTES;
        const uint32_t aB = aStage + (uint32_t)(wm + laneA_row) * 128u;
        const uint32_t bB = bStage + (uint32_t)(wn + laneB_row) * 128u;

        #pragma unroll
        for (int ks = 0; ks < 4; ks++) {   // 4 x k16 = KT
            uint32_t af[4][4];
            uint32_t bf[8][2];
            #pragma unroll
            for (int mt = 0; mt < 4; mt++)
                ldsm4(af[mt][0], af[mt][1], af[mt][2], af[mt][3],
                      aB + (uint32_t)mt * 2048u + cA[ks]);
            #pragma unroll
            for (int p = 0; p < 4; p++)
                ldsm4(bf[2 * p][0], bf[2 * p][1], bf[2 * p + 1][0], bf[2 * p + 1][1],
                      bB + (uint32_t)p * 2048u + cB[ks]);
            #pragma unroll
            for (int mt = 0; mt < 4; mt++)
                #pragma unroll
                for (int nt = 0; nt < 8; nt++)
                    mma_f16(acc[mt][nt], af[mt], bf[nt]);

            if (ks == 0) {   // overlap cp.async issue with MMA work
                if (kt + 2 < KITERS) {
                    int ws = s + 2; if (ws >= STAGES) ws -= STAGES;
                    issue_stage(ws, kt + 2);
                } else {
                    CP_COMMIT();   // keep group count consistent
                }
            }
        }

        if (++s == STAGES) s = 0;
    }

    // ---- epilogue: bias + store ----
    #pragma unroll
    for (int mt = 0; mt < 4; mt++) {
        int m = m0 + wm + mt * 16 + g;
        float* r0 = out + (size_t)m * N_DIM + n0 + wn;
        float* r1 = r0 + (size_t)8 * N_DIM;
        #pragma unroll
        for (int nt = 0; nt < 8; nt++) {
            float2 v0, v1;
            v0.x = acc[mt][nt][0] + bias_r[nt][0];
            v0.y = acc[mt][nt][1] + bias_r[nt][1];
            v1.x = acc[mt][nt][2] + bias_r[nt][0];
            v1.y = acc[mt][nt][3] + bias_r[nt][1];
            *(float2*)(r0 + nt * 8 + 2 * tig) = v0;
            *(float2*)(r1 + nt * 8 + 2 * tig) = v1;
        }
    }
}

// ---------------- launch ----------------
extern "C" void kernel_launch(void* const* d_in, const int* in_sizes, int n_in,
                              void* d_out, int out_size) {
    const float* x = (const float*)d_in[0];       // [8192, 4096]
    const float* w = (const float*)d_in[1];       // [4096, 4096]
    const float* bias = (const float*)d_in[2];    // [4096]
    float* out = (float*)d_out;                   // [8192, 4096]

    prep_kernel<<<XCONV_BLOCKS + WSYM_BLOCKS, 256>>>(x, w);

    cudaFuncSetAttribute(gemm_f16_kernel,
                         cudaFuncAttributeMaxDynamicSharedMemorySize, SMEM_BYTES);
    const int grid = (M_DIM / MT) * (N_DIM / NT);  // 2048
    gemm_f16_kernel<<<grid, THREADS, SMEM_BYTES>>>(bias, out);
}